// round 8
// baseline (speedup 1.0000x reference)
#include <cuda_runtime.h>
#include <cuda_fp16.h>

#define NN 100000
#define NE 1600000
#define NF 256
#define NH 128
#define NC 8

#define NB_XW 782          // xw blocks: 128 rows each (782*128 = 100096)
#define NB_DEG 1563        // deg blocks: 1024 edges each

// Scratch (static __device__ — no runtime allocation allowed)
__device__ __align__(16) float  d_g[NN * NC];    // raw X @ Wc (f32), 3.2 MB
__device__ __align__(16) __half d_gh[NN * NC];   // fp16(g * dinv_src), 1.6 MB L2-resident
__device__ __align__(16) float d_acc[NN * NC];   // raw edge sums; zero at load, re-zeroed by k_post
__device__ int   d_deg[NN];                      // zero at load; re-zeroed by k_scale
__device__ float d_dinv[NN];
__device__ __align__(16) float d_Wc[NF * NC];    // W1 @ Wfc
__device__ __align__(16) float d_bc[NC];         // b1 @ Wfc + bfc

// Detect whether edge_index is int64 (every odd 32-bit word == 0) or int32.
__device__ __forceinline__ bool ei_is64(const int* __restrict__ ei32) {
    return (__ldg(ei32 + 1) == 0) && (__ldg(ei32 + 3) == 0);
}

// ------- k1: fold the two linear layers (tiny) -------
__global__ void k_fold(const float* __restrict__ W1, const float* __restrict__ b1,
                       const float* __restrict__ Wfc, const float* __restrict__ bfc) {
    int t = blockIdx.x * blockDim.x + threadIdx.x;
    if (t < NF * NC) {
        int k = t >> 3, c = t & 7;
        float s = 0.f;
        #pragma unroll 8
        for (int j = 0; j < NH; j++)
            s = fmaf(__ldg(W1 + k * NH + j), __ldg(Wfc + j * NC + c), s);
        d_Wc[t] = s;
    }
    if (t < NC) {
        float s = bfc[t];
        for (int j = 0; j < NH; j++) s = fmaf(b1[j], Wfc[j * NC + t], s);
        d_bc[t] = s;
    }
}

// ------- k2 (fat): g = X @ Wc (raw f32)  CONCURRENT WITH  degree histogram -------
__global__ void __launch_bounds__(256) k_fat(const float* __restrict__ x,
                                             const int* __restrict__ ei32) {
    __shared__ float sw[NF * NC];      // 8 KB, xw branch only
    int t = threadIdx.x;

    if (blockIdx.x < NB_XW) {
        // ---- xw branch: 128 rows/block, 2 threads/row (4 cols each) ----
        #pragma unroll
        for (int i = 0; i < 2; i++)
            ((float4*)sw)[t + i * 256] = ((const float4*)d_Wc)[t + i * 256];
        __syncthreads();

        int row = blockIdx.x * 128 + (t >> 1);
        if (row >= NN) return;
        int half = t & 1;

        const float4* xr = (const float4*)(x + (size_t)row * NF);
        const float4* wp = (const float4*)(sw + half * 4);
        float4 acc = make_float4(0.f, 0.f, 0.f, 0.f);
        #pragma unroll 8
        for (int k4 = 0; k4 < 64; k4++) {
            float4 xv = __ldg(xr + k4);
            float4 w0 = wp[(k4 * 4 + 0) * 2];
            float4 w1 = wp[(k4 * 4 + 1) * 2];
            float4 w2 = wp[(k4 * 4 + 2) * 2];
            float4 w3 = wp[(k4 * 4 + 3) * 2];
            acc.x = fmaf(xv.x, w0.x, acc.x); acc.y = fmaf(xv.x, w0.y, acc.y);
            acc.z = fmaf(xv.x, w0.z, acc.z); acc.w = fmaf(xv.x, w0.w, acc.w);
            acc.x = fmaf(xv.y, w1.x, acc.x); acc.y = fmaf(xv.y, w1.y, acc.y);
            acc.z = fmaf(xv.y, w1.z, acc.z); acc.w = fmaf(xv.y, w1.w, acc.w);
            acc.x = fmaf(xv.z, w2.x, acc.x); acc.y = fmaf(xv.z, w2.y, acc.y);
            acc.z = fmaf(xv.z, w2.z, acc.z); acc.w = fmaf(xv.z, w2.w, acc.w);
            acc.x = fmaf(xv.w, w3.x, acc.x); acc.y = fmaf(xv.w, w3.y, acc.y);
            acc.z = fmaf(xv.w, w3.z, acc.z); acc.w = fmaf(xv.w, w3.w, acc.w);
        }
        ((float4*)d_g)[row * 2 + half] = acc;
    } else {
        // ---- degree branch: 4 edges/thread ----
        int e4 = (blockIdx.x - NB_XW) * 256 + t;
        if (4 * e4 >= NE) return;
        bool is64 = ei_is64(ei32);
        int d0, d1, d2, d3;
        if (is64) {
            const int4* p = (const int4*)(ei32 + 2 * (size_t)NE);
            int4 a = p[e4 * 2], b = p[e4 * 2 + 1];
            d0 = a.x; d1 = a.z; d2 = b.x; d3 = b.z;
        } else {
            int4 a = ((const int4*)(ei32 + NE))[e4];
            d0 = a.x; d1 = a.y; d2 = a.z; d3 = a.w;
        }
        atomicAdd(&d_deg[d0], 1);
        atomicAdd(&d_deg[d1], 1);
        atomicAdd(&d_deg[d2], 1);
        atomicAdd(&d_deg[d3], 1);
    }
}

// ------- k3: gh = fp16(g * dinv); dinv; deg reset (L2 streaming) -------
__global__ void k_scale() {
    int row = blockIdx.x * blockDim.x + threadIdx.x;
    if (row >= NN) return;
    int deg = d_deg[row] + 1;               // +1 self-loop
    float dv = rsqrtf((float)deg);
    float4 g0 = ((const float4*)d_g)[row * 2];
    float4 g1 = ((const float4*)d_g)[row * 2 + 1];
    __half2 h0 = __floats2half2_rn(g0.x * dv, g0.y * dv);
    __half2 h1 = __floats2half2_rn(g0.z * dv, g0.w * dv);
    __half2 h2 = __floats2half2_rn(g1.x * dv, g1.y * dv);
    __half2 h3 = __floats2half2_rn(g1.z * dv, g1.w * dv);
    ((uint4*)d_gh)[row] = make_uint4(*(unsigned*)&h0, *(unsigned*)&h1,
                                     *(unsigned*)&h2, *(unsigned*)&h3);
    d_dinv[row] = dv;
    d_deg[row] = 0;                         // reset for next graph replay
}

// ------- k4: edges -> raw sums. 4 edges/thread; gather gh_s, RED into acc_d -------
__global__ void __launch_bounds__(256) k_edges(const int* __restrict__ ei32) {
    int t = blockIdx.x * blockDim.x + threadIdx.x;     // handles edges 4t..4t+3
    if (4 * t >= NE) return;
    bool is64 = ei_is64(ei32);
    int s[4], d[4];
    if (is64) {
        const int4* ps = (const int4*)ei32;
        const int4* pd = (const int4*)(ei32 + 2 * (size_t)NE);
        int4 a = ps[t * 2], b = ps[t * 2 + 1];
        int4 c = pd[t * 2], e = pd[t * 2 + 1];
        s[0] = a.x; s[1] = a.z; s[2] = b.x; s[3] = b.z;
        d[0] = c.x; d[1] = c.z; d[2] = e.x; d[3] = e.z;
    } else {
        int4 a = ((const int4*)ei32)[t];
        int4 b = ((const int4*)(ei32 + NE))[t];
        s[0] = a.x; s[1] = a.y; s[2] = a.z; s[3] = a.w;
        d[0] = b.x; d[1] = b.y; d[2] = b.z; d[3] = b.w;
    }
    const uint4* gp = (const uint4*)d_gh;
    uint4 gv[4];
    #pragma unroll
    for (int i = 0; i < 4; i++) gv[i] = __ldg(gp + s[i]);   // 4 independent gathers

    #pragma unroll
    for (int i = 0; i < 4; i++) {
        float2 f0 = __half22float2(*(const __half2*)&gv[i].x);
        float2 f1 = __half22float2(*(const __half2*)&gv[i].y);
        float2 f2 = __half22float2(*(const __half2*)&gv[i].z);
        float2 f3 = __half22float2(*(const __half2*)&gv[i].w);
        float4* o = ((float4*)d_acc) + d[i] * 2;
        asm volatile("red.global.add.v4.f32 [%0], {%1, %2, %3, %4};"
                     :: "l"(o), "f"(f0.x), "f"(f0.y), "f"(f1.x), "f"(f1.y) : "memory");
        asm volatile("red.global.add.v4.f32 [%0], {%1, %2, %3, %4};"
                     :: "l"(o + 1), "f"(f2.x), "f"(f2.y), "f"(f3.x), "f"(f3.y) : "memory");
    }
}

// ------- k5: out = bc + dinv * (acc + gh);  acc reset for next replay -------
__global__ void k_post(float* __restrict__ out) {
    int row = blockIdx.x * blockDim.x + threadIdx.x;
    if (row >= NN) return;
    float dv = d_dinv[row];
    float4 s0 = ((const float4*)d_acc)[row * 2];
    float4 s1 = ((const float4*)d_acc)[row * 2 + 1];
    uint4 g = ((const uint4*)d_gh)[row];
    float2 g0 = __half22float2(*(const __half2*)&g.x);
    float2 g1 = __half22float2(*(const __half2*)&g.y);
    float2 g2 = __half22float2(*(const __half2*)&g.z);
    float2 g3 = __half22float2(*(const __half2*)&g.w);
    float4 b0 = ((const float4*)d_bc)[0];
    float4 b1 = ((const float4*)d_bc)[1];
    ((float4*)out)[row * 2] = make_float4(
        fmaf(dv, s0.x + g0.x, b0.x), fmaf(dv, s0.y + g0.y, b0.y),
        fmaf(dv, s0.z + g1.x, b0.z), fmaf(dv, s0.w + g1.y, b0.w));
    ((float4*)out)[row * 2 + 1] = make_float4(
        fmaf(dv, s1.x + g2.x, b1.x), fmaf(dv, s1.y + g2.y, b1.y),
        fmaf(dv, s1.z + g3.x, b1.z), fmaf(dv, s1.w + g3.y, b1.w));
    float4 z = make_float4(0.f, 0.f, 0.f, 0.f);
    ((float4*)d_acc)[row * 2] = z;          // reset for next graph replay
    ((float4*)d_acc)[row * 2 + 1] = z;
}

extern "C" void kernel_launch(void* const* d_in, const int* in_sizes, int n_in,
                              void* d_out, int out_size) {
    const float* x    = (const float*)d_in[0];
    const int*   ei32 = (const int*)d_in[1];   // [2, NE], int32 or int64 (auto-detected)
    const float* W1   = (const float*)d_in[2];
    const float* b1   = (const float*)d_in[3];
    const float* Wfc  = (const float*)d_in[4];
    const float* bfc  = (const float*)d_in[5];
    float* out        = (float*)d_out;

    k_fold<<<8, 256>>>(W1, b1, Wfc, bfc);
    k_fat<<<NB_XW + NB_DEG, 256>>>(x, ei32);
    k_scale<<<(NN + 255) / 256, 256>>>();
    k_edges<<<(NE / 4 + 255) / 256, 256>>>(ei32);
    k_post<<<(NN + 255) / 256, 256>>>(out);
}

// round 9
// speedup vs baseline: 1.0476x; 1.0476x over previous
#include <cuda_runtime.h>
#include <cuda_fp16.h>

#define NN 100000
#define NE 1600000
#define NF 256
#define NH 128
#define NC 8

#define NB_FOLD 8
#define NB_DEG 3125       // deg blocks: 512 edges each (2 edges/thread)

// Scratch (static __device__ — no runtime allocation allowed)
__device__ __align__(16) __half d_gh[NN * NC];   // fp16(g * dinv_src), 1.6 MB L2-resident
__device__ __align__(16) float d_acc[NN * NC];   // raw edge sums; zero at load, re-zeroed by k_post
__device__ int   d_deg[NN];                      // zero at load; re-zeroed by k_xw
__device__ float d_dinv[NN];
__device__ __align__(16) float d_Wc[NF * NC];    // W1 @ Wfc
__device__ __align__(16) float d_bc[NC];         // b1 @ Wfc + bfc

// Detect whether edge_index is int64 (every odd 32-bit word == 0) or int32.
__device__ __forceinline__ bool ei_is64(const int* __restrict__ ei32) {
    return (__ldg(ei32 + 1) == 0) && (__ldg(ei32 + 3) == 0);
}

// ------- k1: weight fold (blocks 0..7) || degree histogram 2 edges/thread (rest) -------
__global__ void __launch_bounds__(256) k_pre(const int* __restrict__ ei32,
                                             const float* __restrict__ W1,
                                             const float* __restrict__ b1,
                                             const float* __restrict__ Wfc,
                                             const float* __restrict__ bfc) {
    int t = threadIdx.x;
    if (blockIdx.x < NB_FOLD) {
        int idx = blockIdx.x * 256 + t;
        if (idx < NF * NC) {
            int k = idx >> 3, c = idx & 7;
            float s = 0.f;
            #pragma unroll 8
            for (int j = 0; j < NH; j++)
                s = fmaf(__ldg(W1 + k * NH + j), __ldg(Wfc + j * NC + c), s);
            d_Wc[idx] = s;
        }
        if (idx < NC) {
            float s = bfc[idx];
            for (int j = 0; j < NH; j++) s = fmaf(b1[j], Wfc[j * NC + idx], s);
            d_bc[idx] = s;
        }
    } else {
        int e2 = (blockIdx.x - NB_FOLD) * 256 + t;     // handles edges 2*e2, 2*e2+1
        if (2 * e2 >= NE) return;
        bool is64 = ei_is64(ei32);
        int d0, d1;
        if (is64) {
            int4 a = ((const int4*)(ei32 + 2 * (size_t)NE))[e2];
            d0 = a.x; d1 = a.z;
        } else {
            int2 a = ((const int2*)(ei32 + NE))[e2];
            d0 = a.x; d1 = a.y;
        }
        atomicAdd(&d_deg[d0], 1);
        atomicAdd(&d_deg[d1], 1);
    }
}

// ------- k2: gh = fp16((X @ Wc) * dinv); dinv; deg reset -------
// 128 rows/block, 2 threads/row (4 columns each).
__global__ void __launch_bounds__(256) k_xw(const float* __restrict__ x) {
    __shared__ float sw[NF * NC];      // 8 KB
    int t = threadIdx.x;
    #pragma unroll
    for (int i = 0; i < 2; i++)
        ((float4*)sw)[t + i * 256] = ((const float4*)d_Wc)[t + i * 256];
    __syncthreads();

    int row = blockIdx.x * 128 + (t >> 1);
    if (row >= NN) return;
    int half = t & 1;                       // columns 4*half .. 4*half+3

    const float4* xr = (const float4*)(x + (size_t)row * NF);
    const float4* wp = (const float4*)(sw + half * 4);   // stride 2 float4s per k
    float4 acc = make_float4(0.f, 0.f, 0.f, 0.f);
    #pragma unroll 8
    for (int k4 = 0; k4 < 64; k4++) {
        float4 xv = __ldg(xr + k4);
        float4 w0 = wp[(k4 * 4 + 0) * 2];
        float4 w1 = wp[(k4 * 4 + 1) * 2];
        float4 w2 = wp[(k4 * 4 + 2) * 2];
        float4 w3 = wp[(k4 * 4 + 3) * 2];
        acc.x = fmaf(xv.x, w0.x, acc.x); acc.y = fmaf(xv.x, w0.y, acc.y);
        acc.z = fmaf(xv.x, w0.z, acc.z); acc.w = fmaf(xv.x, w0.w, acc.w);
        acc.x = fmaf(xv.y, w1.x, acc.x); acc.y = fmaf(xv.y, w1.y, acc.y);
        acc.z = fmaf(xv.y, w1.z, acc.z); acc.w = fmaf(xv.y, w1.w, acc.w);
        acc.x = fmaf(xv.z, w2.x, acc.x); acc.y = fmaf(xv.z, w2.y, acc.y);
        acc.z = fmaf(xv.z, w2.z, acc.z); acc.w = fmaf(xv.z, w2.w, acc.w);
        acc.x = fmaf(xv.w, w3.x, acc.x); acc.y = fmaf(xv.w, w3.y, acc.y);
        acc.z = fmaf(xv.w, w3.z, acc.z); acc.w = fmaf(xv.w, w3.w, acc.w);
    }

    int deg = d_deg[row] + 1;               // +1 self-loop (L1 broadcast for the pair)
    float dv = rsqrtf((float)deg);
    __half2 h0 = __floats2half2_rn(acc.x * dv, acc.y * dv);
    __half2 h1 = __floats2half2_rn(acc.z * dv, acc.w * dv);
    ((uint2*)d_gh)[row * 2 + half] = make_uint2(*(unsigned*)&h0, *(unsigned*)&h1);
    if (half == 0) {
        d_dinv[row] = dv;
        d_deg[row] = 0;                     // reset for next graph replay
    }
}

// ------- k3: edges -> raw sums. 2 edges/thread; gather gh_s, RED into acc_d -------
__global__ void k_edges(const int* __restrict__ ei32) {
    int t = blockIdx.x * blockDim.x + threadIdx.x;     // handles edges 2t, 2t+1
    if (2 * t >= NE) return;
    bool is64 = ei_is64(ei32);
    int s0, s1, d0, d1;
    if (is64) {
        int4 a = ((const int4*)ei32)[t];
        int4 b = ((const int4*)(ei32 + 2 * (size_t)NE))[t];
        s0 = a.x; s1 = a.z; d0 = b.x; d1 = b.z;
    } else {
        int2 a = ((const int2*)ei32)[t];
        int2 b = ((const int2*)(ei32 + NE))[t];
        s0 = a.x; s1 = a.y; d0 = b.x; d1 = b.y;
    }
    const uint4* gp = (const uint4*)d_gh;
    uint4 ga = __ldg(gp + s0);
    uint4 gb = __ldg(gp + s1);

    float2 a0 = __half22float2(*(const __half2*)&ga.x);
    float2 a1 = __half22float2(*(const __half2*)&ga.y);
    float2 a2 = __half22float2(*(const __half2*)&ga.z);
    float2 a3 = __half22float2(*(const __half2*)&ga.w);
    float2 c0 = __half22float2(*(const __half2*)&gb.x);
    float2 c1 = __half22float2(*(const __half2*)&gb.y);
    float2 c2 = __half22float2(*(const __half2*)&gb.z);
    float2 c3 = __half22float2(*(const __half2*)&gb.w);

    float4* oa = ((float4*)d_acc) + d0 * 2;
    float4* ob = ((float4*)d_acc) + d1 * 2;
    asm volatile("red.global.add.v4.f32 [%0], {%1, %2, %3, %4};"
                 :: "l"(oa), "f"(a0.x), "f"(a0.y), "f"(a1.x), "f"(a1.y) : "memory");
    asm volatile("red.global.add.v4.f32 [%0], {%1, %2, %3, %4};"
                 :: "l"(oa + 1), "f"(a2.x), "f"(a2.y), "f"(a3.x), "f"(a3.y) : "memory");
    asm volatile("red.global.add.v4.f32 [%0], {%1, %2, %3, %4};"
                 :: "l"(ob), "f"(c0.x), "f"(c0.y), "f"(c1.x), "f"(c1.y) : "memory");
    asm volatile("red.global.add.v4.f32 [%0], {%1, %2, %3, %4};"
                 :: "l"(ob + 1), "f"(c2.x), "f"(c2.y), "f"(c3.x), "f"(c3.y) : "memory");
}

// ------- k4: out = bc + dinv * (acc + gh);  acc reset for next replay -------
__global__ void k_post(float* __restrict__ out) {
    int row = blockIdx.x * blockDim.x + threadIdx.x;
    if (row >= NN) return;
    float dv = d_dinv[row];
    float4 s0 = ((const float4*)d_acc)[row * 2];
    float4 s1 = ((const float4*)d_acc)[row * 2 + 1];
    uint4 g = ((const uint4*)d_gh)[row];
    float2 g0 = __half22float2(*(const __half2*)&g.x);
    float2 g1 = __half22float2(*(const __half2*)&g.y);
    float2 g2 = __half22float2(*(const __half2*)&g.z);
    float2 g3 = __half22float2(*(const __half2*)&g.w);
    float4 b0 = ((const float4*)d_bc)[0];
    float4 b1 = ((const float4*)d_bc)[1];
    ((float4*)out)[row * 2] = make_float4(
        fmaf(dv, s0.x + g0.x, b0.x), fmaf(dv, s0.y + g0.y, b0.y),
        fmaf(dv, s0.z + g1.x, b0.z), fmaf(dv, s0.w + g1.y, b0.w));
    ((float4*)out)[row * 2 + 1] = make_float4(
        fmaf(dv, s1.x + g2.x, b1.x), fmaf(dv, s1.y + g2.y, b1.y),
        fmaf(dv, s1.z + g3.x, b1.z), fmaf(dv, s1.w + g3.y, b1.w));
    float4 z = make_float4(0.f, 0.f, 0.f, 0.f);
    ((float4*)d_acc)[row * 2] = z;          // reset for next graph replay
    ((float4*)d_acc)[row * 2 + 1] = z;
}

extern "C" void kernel_launch(void* const* d_in, const int* in_sizes, int n_in,
                              void* d_out, int out_size) {
    const float* x    = (const float*)d_in[0];
    const int*   ei32 = (const int*)d_in[1];   // [2, NE], int32 or int64 (auto-detected)
    const float* W1   = (const float*)d_in[2];
    const float* b1   = (const float*)d_in[3];
    const float* Wfc  = (const float*)d_in[4];
    const float* bfc  = (const float*)d_in[5];
    float* out        = (float*)d_out;

    k_pre<<<NB_FOLD + NB_DEG, 256>>>(ei32, W1, b1, Wfc, bfc);
    k_xw<<<(NN + 127) / 128, 256>>>(x);
    k_edges<<<(NE / 2 + 255) / 256, 256>>>(ei32);
    k_post<<<(NN + 255) / 256, 256>>>(out);
}